// round 1
// baseline (speedup 1.0000x reference)
#include <cuda_runtime.h>
#include <cstdint>

// KDPointToPointLoss: loss[b] = (1/(3N)) * sum_n min_m ||s[b,:,n] - t[b,:,m]||^2
// Shapes fixed by the dataset: B=8, C=3, N=M=4096.

#define BATCH 8
#define NPTS  4096
#define MPTS  4096

#define TC        512                 // targets per chunk (smem float4 = 8KB)
#define THREADS   128
#define ILP       2                   // source points per thread
#define SRC_PER_BLOCK (THREADS * ILP) // 256
#define SRC_CHUNKS (NPTS / SRC_PER_BLOCK) // 16
#define TGT_CHUNKS (MPTS / TC)            // 8

// Per-(batch, source-point) running min of squared distance, as uint bits.
// d2 is clamped >= 0, so uint ordering == float ordering.
__device__ unsigned int g_min[BATCH * NPTS];

__global__ void init_kernel() {
    int i = blockIdx.x * blockDim.x + threadIdx.x;
    if (i < BATCH * NPTS) g_min[i] = 0x7F800000u;  // +inf
}

__global__ __launch_bounds__(THREADS) void nn_kernel(
    const float* __restrict__ src, const float* __restrict__ tgt) {
    __shared__ float4 st[TC];

    const int b    = blockIdx.z;
    const int tgt0 = blockIdx.x * TC;
    const int src0 = blockIdx.y * SRC_PER_BLOCK;

    // Cooperative load of this target chunk: (x, y, z, |t|^2) per target.
    const float* tb = tgt + (size_t)b * 3 * MPTS;
    for (int j = threadIdx.x; j < TC; j += THREADS) {
        float x = tb[0 * MPTS + tgt0 + j];
        float y = tb[1 * MPTS + tgt0 + j];
        float z = tb[2 * MPTS + tgt0 + j];
        st[j] = make_float4(x, y, z, fmaf(x, x, fmaf(y, y, z * z)));
    }
    __syncthreads();

    // Per-thread source points: coefficients c = -2*s, plus |s|^2.
    const float* sb = src + (size_t)b * 3 * NPTS;
    float cx[ILP], cy[ILP], cz[ILP], s2[ILP], mn[ILP];
#pragma unroll
    for (int p = 0; p < ILP; p++) {
        int n = src0 + p * THREADS + threadIdx.x;
        float sx = sb[0 * NPTS + n];
        float sy = sb[1 * NPTS + n];
        float sz = sb[2 * NPTS + n];
        cx[p] = -2.0f * sx;
        cy[p] = -2.0f * sy;
        cz[p] = -2.0f * sz;
        s2[p] = fmaf(sx, sx, fmaf(sy, sy, sz * sz));
        mn[p] = 1e30f;
    }

    // Main loop: score = |t|^2 - 2 s.t  (= d2 - |s|^2, monotone in d2).
    // 3 FFMA (fma pipe) + 1 FMNMX (alu pipe) per pair; float4 broadcast from smem.
#pragma unroll 8
    for (int j = 0; j < TC; j++) {
        float4 t = st[j];
#pragma unroll
        for (int p = 0; p < ILP; p++) {
            float sc = fmaf(cx[p], t.x, fmaf(cy[p], t.y, fmaf(cz[p], t.z, t.w)));
            mn[p] = fminf(mn[p], sc);
        }
    }

    // Combine partial mins across target chunks. d2 >= 0 after clamp, so
    // uint-bit atomicMin implements float min exactly (deterministic).
#pragma unroll
    for (int p = 0; p < ILP; p++) {
        int n = src0 + p * THREADS + threadIdx.x;
        float d2 = fmaxf(mn[p] + s2[p], 0.0f);
        atomicMin(&g_min[b * NPTS + n], __float_as_uint(d2));
    }
}

__global__ void reduce_kernel(float* __restrict__ out) {
    __shared__ float sh[256];
    const int b = blockIdx.x;
    float s = 0.0f;
    for (int i = threadIdx.x; i < NPTS; i += 256)
        s += __uint_as_float(g_min[b * NPTS + i]);
    sh[threadIdx.x] = s;
    __syncthreads();
    for (int o = 128; o > 0; o >>= 1) {
        if (threadIdx.x < o) sh[threadIdx.x] += sh[threadIdx.x + o];
        __syncthreads();
    }
    if (threadIdx.x == 0) out[b] = sh[0] * (1.0f / (3.0f * NPTS));
}

extern "C" void kernel_launch(void* const* d_in, const int* in_sizes, int n_in,
                              void* d_out, int out_size) {
    const float* src = (const float*)d_in[0];  // [B,3,N]
    const float* tgt = (const float*)d_in[1];  // [B,3,M]
    float* out = (float*)d_out;                // [B]

    init_kernel<<<(BATCH * NPTS + 255) / 256, 256>>>();

    dim3 grid(TGT_CHUNKS, SRC_CHUNKS, BATCH);  // 8 x 16 x 8 = 1024 blocks
    nn_kernel<<<grid, THREADS>>>(src, tgt);

    reduce_kernel<<<BATCH, 256>>>(out);
}